// round 3
// baseline (speedup 1.0000x reference)
#include <cuda_runtime.h>
#include <cuda_bf16.h>

#define N_RAYS 65536
#define N_PTS  128
#define WARPS_PER_BLOCK 8
#define RAYS_PER_WARP 4

struct RayRegs {
    float4 dp, dn, f0, f1, f2;
};

__device__ __forceinline__ void load_ray(int ray, int lane,
                                         const float* __restrict__ density,
                                         const float* __restrict__ feature,
                                         const float* __restrict__ depth,
                                         RayRegs& r)
{
    const float4* dep4 = reinterpret_cast<const float4*>(depth   + (size_t)ray * N_PTS);
    const float4* den4 = reinterpret_cast<const float4*>(density + (size_t)ray * N_PTS);
    const float4* f4   = reinterpret_cast<const float4*>(feature + (size_t)ray * (N_PTS * 3)) + lane * 3;
    r.dp = __ldcs(dep4 + lane);
    r.dn = __ldcs(den4 + lane);
    r.f0 = __ldcs(f4 + 0);
    r.f1 = __ldcs(f4 + 1);
    r.f2 = __ldcs(f4 + 2);
}

__device__ __forceinline__ void compute_ray(int ray, int lane, const RayRegs& rr,
                                            float* __restrict__ out)
{
    const unsigned FULL = 0xffffffffu;

    // deltas (boundary sample from next lane; lane31 last = 1e10)
    float nxt = __shfl_down_sync(FULL, rr.dp.x, 1);
    float dv[4]   = { rr.dp.x, rr.dp.y, rr.dp.z, rr.dp.w };
    float dens[4] = { rr.dn.x, rr.dn.y, rr.dn.z, rr.dn.w };
    float delta[4];
    delta[0] = rr.dp.y - rr.dp.x;
    delta[1] = rr.dp.z - rr.dp.y;
    delta[2] = rr.dp.w - rr.dp.z;
    delta[3] = (lane == 31) ? 1e10f : (nxt - rr.dp.w);

    // alpha and (1 - alpha + eps) = exp(-delta*sigma) + eps
    float alpha[4], a[4];
    #pragma unroll
    for (int k = 0; k < 4; k++) {
        float e  = __expf(-delta[k] * dens[k]);
        alpha[k] = 1.0f - e;
        a[k]     = e + 1e-10f;
    }

    // local exclusive prefix products within the lane's 4 samples
    float lp1 = a[0];
    float lp2 = lp1 * a[1];
    float lp3 = lp2 * a[2];
    float lane_prod = lp3 * a[3];

    // warp inclusive scan (product) over lane products
    float scan = lane_prod;
    #pragma unroll
    for (int d = 1; d < 32; d <<= 1) {
        float v = __shfl_up_sync(FULL, scan, d);
        if (lane >= d) scan *= v;
    }
    float excl = __shfl_up_sync(FULL, scan, 1);
    if (lane == 0) excl = 1.0f;

    // per-sample features
    float fr[4] = { rr.f0.x, rr.f0.w, rr.f1.z, rr.f2.y };
    float fg[4] = { rr.f0.y, rr.f1.x, rr.f1.w, rr.f2.z };
    float fb[4] = { rr.f0.z, rr.f1.y, rr.f2.x, rr.f2.w };

    float lpk[4] = { 1.0f, lp1, lp2, lp3 };
    float r = 0.f, g = 0.f, b = 0.f, ds = 0.f;
    #pragma unroll
    for (int k = 0; k < 4; k++) {
        float w = excl * lpk[k] * alpha[k];
        r  += w * fr[k];
        g  += w * fg[k];
        b  += w * fb[k];
        ds += w * dv[k];
    }

    // warp butterfly reduction
    #pragma unroll
    for (int off = 16; off; off >>= 1) {
        r  += __shfl_xor_sync(FULL, r,  off);
        g  += __shfl_xor_sync(FULL, g,  off);
        b  += __shfl_xor_sync(FULL, b,  off);
        ds += __shfl_xor_sync(FULL, ds, off);
    }

    if (lane == 0) {
        float* rgb = out + (size_t)ray * 3;
        rgb[0] = r; rgb[1] = g; rgb[2] = b;
        float* dout = out + (size_t)N_RAYS * 3 + (size_t)ray * 3;
        dout[0] = ds; dout[1] = ds; dout[2] = ds;
    }
}

__global__ __launch_bounds__(32 * WARPS_PER_BLOCK)
void volrend_kernel(const float* __restrict__ density,
                    const float* __restrict__ feature,
                    const float* __restrict__ depth,
                    float* __restrict__ out)
{
    int lane = threadIdx.x & 31;
    int wid  = threadIdx.x >> 5;
    int base = (blockIdx.x * WARPS_PER_BLOCK + wid) * RAYS_PER_WARP;

    RayRegs cur, nxt;
    load_ray(base, lane, density, feature, depth, cur);

    #pragma unroll
    for (int i = 0; i < RAYS_PER_WARP; i++) {
        if (i + 1 < RAYS_PER_WARP)
            load_ray(base + i + 1, lane, density, feature, depth, nxt);
        compute_ray(base + i, lane, cur, out);
        cur = nxt;
    }
}

extern "C" void kernel_launch(void* const* d_in, const int* in_sizes, int n_in,
                              void* d_out, int out_size)
{
    const float* density = (const float*)d_in[0];
    const float* feature = (const float*)d_in[1];
    const float* depth   = (const float*)d_in[2];
    float* out = (float*)d_out;

    int blocks = N_RAYS / (WARPS_PER_BLOCK * RAYS_PER_WARP);  // 2048
    volrend_kernel<<<blocks, 32 * WARPS_PER_BLOCK>>>(density, feature, depth, out);
}